// round 13
// baseline (speedup 1.0000x reference)
#include <cuda_runtime.h>

#define NROWS 8192
#define NDIM  512
#define ND4   128      // NDIM/4
#define NTOP  100
#define NBLK  256
#define NTHR  512
#define RPB   32       // rows per block
#define NBIN  4096
#define CAP   1536

#define SMEM_X_BYTES   (RPB * ND4 * 16)         // 64 KB: block's 32 rows
#define SMEM_ACC_BYTES (8 * ND4 * 16)           // 16 KB scratch
#define SMEM_TOTAL     (SMEM_X_BYTES + SMEM_ACC_BYTES)

__device__ float4 g_s4[ND4];
__device__ int   g_hist[NBIN];
__device__ unsigned int g_key[NROWS];
__device__ unsigned int g_sync[3];  // [0] s ctr, [1] key+hist ctr, [2] done ctr

__device__ __forceinline__ unsigned int vload(unsigned int* p) {
    return *(volatile unsigned int*)p;
}

__global__ void __launch_bounds__(NTHR, 2) kFused(const float4* __restrict__ x4,
                                                  float* __restrict__ out,
                                                  float4* __restrict__ out4,
                                                  int out_size) {
    extern __shared__ char smem_raw[];
    float4* xs    = (float4*)smem_raw;                       // [32][ND4]
    float4* sacc  = (float4*)(smem_raw + SMEM_X_BYTES);      // [8][ND4]
    float*  saccf = (float*)sacc;

    __shared__ int swarp[16];
    __shared__ int sh_B, sh_ncand;
    __shared__ int s_row;

    const int t    = threadIdx.x;
    const int wid  = t >> 5;          // 0..15
    const int lane = t & 31;
    const int lrow0 = wid * 2;

    // ===== P1: stream 2 rows/warp to smem, per-row 1/||x||, colsum partial ===
    float rinv0, rinv1;
    {
        const float4* r0 = x4 + (size_t)(blockIdx.x * RPB + lrow0) * ND4;
        const float4* r1 = r0 + ND4;
        float4 v0[4], v1[4];
        #pragma unroll
        for (int k = 0; k < 4; ++k) v0[k] = r0[lane + 32 * k];
        #pragma unroll
        for (int k = 0; k < 4; ++k) v1[k] = r1[lane + 32 * k];
        #pragma unroll
        for (int k = 0; k < 4; ++k) xs[lrow0 * ND4 + lane + 32 * k] = v0[k];
        #pragma unroll
        for (int k = 0; k < 4; ++k) xs[(lrow0 + 1) * ND4 + lane + 32 * k] = v1[k];

        float sq0 = 0.f, sq1 = 0.f;
        #pragma unroll
        for (int k = 0; k < 4; ++k) {
            sq0 += v0[k].x*v0[k].x + v0[k].y*v0[k].y + v0[k].z*v0[k].z + v0[k].w*v0[k].w;
            sq1 += v1[k].x*v1[k].x + v1[k].y*v1[k].y + v1[k].z*v1[k].z + v1[k].w*v1[k].w;
        }
        #pragma unroll
        for (int o = 16; o; o >>= 1) {
            sq0 += __shfl_xor_sync(0xffffffffu, sq0, o);
            sq1 += __shfl_xor_sync(0xffffffffu, sq1, o);
        }
        rinv0 = rsqrtf(sq0); rinv0 = rinv0 * (1.5f - 0.5f * sq0 * rinv0 * rinv0);
        rinv1 = rsqrtf(sq1); rinv1 = rinv1 * (1.5f - 0.5f * sq1 * rinv1 * rinv1);

        float4 acc[4];
        #pragma unroll
        for (int k = 0; k < 4; ++k) {
            acc[k].x = fmaf(v0[k].x, rinv0, v1[k].x * rinv1);
            acc[k].y = fmaf(v0[k].y, rinv0, v1[k].y * rinv1);
            acc[k].z = fmaf(v0[k].z, rinv0, v1[k].z * rinv1);
            acc[k].w = fmaf(v0[k].w, rinv0, v1[k].w * rinv1);
        }
        // 16 warps -> 8 smem buffers -> final
        if (wid >= 8) {
            #pragma unroll
            for (int k = 0; k < 4; ++k) sacc[(wid - 8) * ND4 + lane + 32 * k] = acc[k];
        }
        __syncthreads();
        if (wid < 8) {
            #pragma unroll
            for (int k = 0; k < 4; ++k) {
                float4 o = sacc[wid * ND4 + lane + 32 * k];
                acc[k].x += o.x; acc[k].y += o.y; acc[k].z += o.z; acc[k].w += o.w;
                sacc[wid * ND4 + lane + 32 * k] = acc[k];
            }
        }
        __syncthreads();
        if (t < ND4) {
            float4 s = sacc[t];
            #pragma unroll
            for (int w = 1; w < 8; ++w) {
                float4 u = sacc[w * ND4 + t];
                s.x += u.x; s.y += u.y; s.z += u.z; s.w += u.w;
            }
            sacc[t] = s;
        }
        __syncthreads();
        // 512 REDs per block (one per address)
        atomicAdd((float*)g_s4 + t, saccf[t]);
    }

    // ===== SYNC 1: all REDs to g_s complete ===================================
    __syncthreads();
    if (t == 0) {
        __threadfence();
        atomicAdd(&g_sync[0], 1u);
        while (vload(&g_sync[0]) < NBLK) __nanosleep(32);
        __threadfence();
    }
    __syncthreads();

    // ===== P3: s direct from L2; dots from smem x; keys + global hist ========
    {
        float4 sv[4];
        #pragma unroll
        for (int k = 0; k < 4; ++k) sv[k] = g_s4[lane + 32 * k];

        float dot0 = 0.f, dot1 = 0.f;
        #pragma unroll
        for (int k = 0; k < 4; ++k) {
            float4 a = xs[lrow0 * ND4 + lane + 32 * k];
            float4 b = xs[(lrow0 + 1) * ND4 + lane + 32 * k];
            dot0 = fmaf(a.x, sv[k].x, dot0); dot0 = fmaf(a.y, sv[k].y, dot0);
            dot0 = fmaf(a.z, sv[k].z, dot0); dot0 = fmaf(a.w, sv[k].w, dot0);
            dot1 = fmaf(b.x, sv[k].x, dot1); dot1 = fmaf(b.y, sv[k].y, dot1);
            dot1 = fmaf(b.z, sv[k].z, dot1); dot1 = fmaf(b.w, sv[k].w, dot1);
        }
        #pragma unroll
        for (int o = 16; o; o >>= 1) {
            dot0 += __shfl_down_sync(0xffffffffu, dot0, o);
            dot1 += __shfl_down_sync(0xffffffffu, dot1, o);
        }
        if (lane == 0) {
            unsigned int u0 = __float_as_uint(dot0 * rinv0);
            unsigned int u1 = __float_as_uint(dot1 * rinv1);
            u0 = (u0 & 0x80000000u) ? ~u0 : (u0 | 0x80000000u);
            u1 = (u1 & 0x80000000u) ? ~u1 : (u1 | 0x80000000u);
            int row = blockIdx.x * RPB + lrow0;
            *(uint2*)&g_key[row] = make_uint2(u0, u1);
            atomicAdd(&g_hist[u0 >> 20], 1);
            atomicAdd(&g_hist[u1 >> 20], 1);
        }
    }

    // ===== SYNC 2: keys + hist visible. Blocks >= NTOP just arrive. ===========
    __syncthreads();
    if (t == 0) { __threadfence(); atomicAdd(&g_sync[1], 1u); }

    if (blockIdx.x < NTOP) {
        if (t == 0) {
            while (vload(&g_sync[1]) < NBLK) __nanosleep(32);
            __threadfence();
        }
        __syncthreads();

        // ===== P4: hist scan -> boundary bin B ================================
        // thread t owns bins [8t, 8t+8)
        uint4 h0 = ((const uint4*)g_hist)[2 * t];
        uint4 h1 = ((const uint4*)g_hist)[2 * t + 1];
        int hh[8] = {(int)h0.x, (int)h0.y, (int)h0.z, (int)h0.w,
                     (int)h1.x, (int)h1.y, (int)h1.z, (int)h1.w};
        if (t == 0) sh_ncand = 0;

        int lsum = 0;
        #pragma unroll
        for (int i = 0; i < 8; ++i) lsum += hh[i];
        int v = lsum;
        #pragma unroll
        for (int o = 1; o < 32; o <<= 1) {
            int u = __shfl_up_sync(0xffffffffu, v, o);
            if (lane >= o) v += u;
        }
        if (lane == 31) swarp[wid] = v;
        __syncthreads();
        if (t < 16) {
            int w = swarp[t];
            int vv = w;
            #pragma unroll
            for (int o = 1; o < 16; o <<= 1) {
                int u = __shfl_up_sync(0x0000ffffu, vv, o);
                if (lane >= o) vv += u;
            }
            swarp[t] = vv - w;                  // exclusive warp offset
        }
        __syncthreads();
        {
            int c = swarp[wid] + (v - lsum);    // exclusive prefix for bin 8t
            #pragma unroll
            for (int i = 0; i < 8; ++i) {
                int c2 = c + hh[i];
                if (c < NTOP && c2 >= NTOP) sh_B = 8 * t + i;
                c = c2;
            }
        }
        __syncthreads();
        unsigned int B = (unsigned int)sh_B;

        // ===== collect candidates (keys loaded lazily, 16/thread) =============
        unsigned int* ckey = (unsigned int*)sacc;          // [CAP]
        int*          cidx = (int*)sacc + CAP;             // [CAP]
        #pragma unroll
        for (int q = 0; q < 4; ++q) {
            uint4 kv = ((const uint4*)g_key)[t + NTHR * q];
            unsigned int kk[4] = {kv.x, kv.y, kv.z, kv.w};
            #pragma unroll
            for (int j = 0; j < 4; ++j) {
                if ((kk[j] >> 20) <= B) {
                    int p = atomicAdd(&sh_ncand, 1);
                    if (p < CAP) {
                        ckey[p] = kk[j];
                        cidx[p] = 4 * (t + NTHR * q) + j;
                    }
                }
            }
        }
        __syncthreads();
        int nc = sh_ncand < CAP ? sh_ncand : CAP;

        if (t < nc) {
            unsigned int mk = ckey[t];
            int mi = cidx[t];
            int rank = 0;
            for (int j = 0; j < nc; ++j)
                rank += (ckey[j] < mk || (ckey[j] == mk && cidx[j] < mi)) ? 1 : 0;
            if (rank == blockIdx.x) s_row = mi;
        }
        __syncthreads();

        // ===== P5: write this block's row + index =============================
        int row = s_row;
        if (t < ND4) {
            int e = blockIdx.x * ND4 + t;
            if (4 * e + 4 <= out_size)
                out4[e] = x4[(size_t)row * ND4 + t];
        }
        if (t == 0 && NTOP * NDIM + blockIdx.x < out_size)
            out[NTOP * NDIM + blockIdx.x] = (float)row;
    }

    // ===== epilogue: last finisher resets g_s, g_hist, sync for replay ========
    __shared__ int s_reset;
    if (t == 0) {
        __threadfence();
        s_reset = (atomicAdd(&g_sync[2], 1u) == NBLK - 1) ? 1 : 0;
    }
    __syncthreads();
    if (s_reset) {
        if (t < ND4) g_s4[t] = make_float4(0.f, 0.f, 0.f, 0.f);
        #pragma unroll
        for (int j = 0; j < NBIN / NTHR; ++j) g_hist[t + NTHR * j] = 0;
        __syncthreads();
        if (t == 0) {
            *(volatile unsigned int*)&g_sync[0] = 0;
            *(volatile unsigned int*)&g_sync[1] = 0;
            __threadfence();
            *(volatile unsigned int*)&g_sync[2] = 0;
        }
    }
}

extern "C" void kernel_launch(void* const* d_in, const int* in_sizes, int n_in,
                              void* d_out, int out_size) {
    const float4* x4 = (const float4*)d_in[0];
    cudaFuncSetAttribute(kFused, cudaFuncAttributeMaxDynamicSharedMemorySize,
                         SMEM_TOTAL);
    kFused<<<NBLK, NTHR, SMEM_TOTAL>>>(x4, (float*)d_out, (float4*)d_out, out_size);
}

// round 14
// speedup vs baseline: 1.0115x; 1.0115x over previous
#include <cuda_runtime.h>

#define NROWS 8192
#define NDIM  512
#define ND4   128      // NDIM/4
#define NTOP  100
#define NBLK  128
#define NTHR  1024
#define NBIN  4096
#define CAP   1536

#define SMEM_X_BYTES   (64 * ND4 * 16)          // 128 KB: block's 64 rows
#define SMEM_ACC_BYTES (32 * ND4 * 16)          // 64 KB: 32 warp partials
#define SMEM_PS_BYTES  (2 * NDIM * 4)           // 4 KB: 2 float partial rows
#define SMEM_TOTAL     (SMEM_X_BYTES + SMEM_ACC_BYTES + SMEM_PS_BYTES)

__device__ float4 g_s4[ND4];
__device__ int   g_hist[NBIN];
__device__ unsigned int g_key[NROWS];
__device__ unsigned int g_sync[3];  // [0] s ctr, [1] key+hist ctr, [2] done ctr

__device__ __forceinline__ unsigned int vload(unsigned int* p) {
    return *(volatile unsigned int*)p;
}

__global__ void __launch_bounds__(NTHR, 1) kFused(const float4* __restrict__ x4,
                                                  float* __restrict__ out,
                                                  float4* __restrict__ out4,
                                                  int out_size) {
    extern __shared__ char smem_raw[];
    float4* xs    = (float4*)smem_raw;                        // [64][ND4]
    float4* sacc  = (float4*)(smem_raw + SMEM_X_BYTES);       // [32][ND4]
    float*  saccf = (float*)sacc;                             // [32][512]
    float*  psum  = (float*)(smem_raw + SMEM_X_BYTES + SMEM_ACC_BYTES); // [2][512]

    __shared__ int swarp[32];
    __shared__ int sh_B, sh_ncand;
    __shared__ int s_row;

    const int t    = threadIdx.x;
    const int wid  = t >> 5;          // 0..31
    const int lane = t & 31;
    const int lrow0 = wid * 2;

    // ===== P1: stream 2 rows/warp to smem, per-row 1/||x||, colsum partial ===
    float rinv0, rinv1;
    {
        const float4* r0 = x4 + (size_t)(blockIdx.x * 64 + lrow0) * ND4;
        const float4* r1 = r0 + ND4;
        float4 v0[4], v1[4];
        #pragma unroll
        for (int k = 0; k < 4; ++k) v0[k] = r0[lane + 32 * k];
        #pragma unroll
        for (int k = 0; k < 4; ++k) v1[k] = r1[lane + 32 * k];
        #pragma unroll
        for (int k = 0; k < 4; ++k) xs[lrow0 * ND4 + lane + 32 * k] = v0[k];
        #pragma unroll
        for (int k = 0; k < 4; ++k) xs[(lrow0 + 1) * ND4 + lane + 32 * k] = v1[k];

        float sq0 = 0.f, sq1 = 0.f;
        #pragma unroll
        for (int k = 0; k < 4; ++k) {
            sq0 += v0[k].x*v0[k].x + v0[k].y*v0[k].y + v0[k].z*v0[k].z + v0[k].w*v0[k].w;
            sq1 += v1[k].x*v1[k].x + v1[k].y*v1[k].y + v1[k].z*v1[k].z + v1[k].w*v1[k].w;
        }
        #pragma unroll
        for (int o = 16; o; o >>= 1) {
            sq0 += __shfl_xor_sync(0xffffffffu, sq0, o);
            sq1 += __shfl_xor_sync(0xffffffffu, sq1, o);
        }
        rinv0 = rsqrtf(sq0);      // MUFU.RSQ rel err ~2.4e-7 << boundary gap
        rinv1 = rsqrtf(sq1);

        // each warp writes its own partial buffer (no cross-warp combine here)
        #pragma unroll
        for (int k = 0; k < 4; ++k) {
            float4 a;
            a.x = fmaf(v0[k].x, rinv0, v1[k].x * rinv1);
            a.y = fmaf(v0[k].y, rinv0, v1[k].y * rinv1);
            a.z = fmaf(v0[k].z, rinv0, v1[k].z * rinv1);
            a.w = fmaf(v0[k].w, rinv0, v1[k].w * rinv1);
            sacc[wid * ND4 + lane + 32 * k] = a;
        }
        __syncthreads();

        // 1024 threads: d = t&511, group g = t>>9; sum 16 buffers float-wise
        {
            int d = t & (NDIM - 1);
            int g = t >> 9;                    // 0 or 1
            float s = 0.f;
            #pragma unroll
            for (int b = 0; b < 16; ++b) s += saccf[(g * 16 + b) * NDIM + d];
            psum[g * NDIM + d] = s;
        }
        __syncthreads();
        // 512 REDs per block (one per address)
        if (t < NDIM) atomicAdd((float*)g_s4 + t, psum[t] + psum[NDIM + t]);
    }

    // ===== SYNC 1: counter == NBLK  =>  all REDs to g_s complete ==============
    __syncthreads();
    if (t == 0) {
        __threadfence();
        atomicAdd(&g_sync[0], 1u);
        while (vload(&g_sync[0]) < NBLK) __nanosleep(32);
        __threadfence();
    }
    __syncthreads();

    // ===== P3: s direct from L2; dots from smem x; keys + global hist ========
    {
        float4 sv[4];
        #pragma unroll
        for (int k = 0; k < 4; ++k) sv[k] = g_s4[lane + 32 * k];

        float dot0 = 0.f, dot1 = 0.f;
        #pragma unroll
        for (int k = 0; k < 4; ++k) {
            float4 a = xs[lrow0 * ND4 + lane + 32 * k];
            float4 b = xs[(lrow0 + 1) * ND4 + lane + 32 * k];
            dot0 = fmaf(a.x, sv[k].x, dot0); dot0 = fmaf(a.y, sv[k].y, dot0);
            dot0 = fmaf(a.z, sv[k].z, dot0); dot0 = fmaf(a.w, sv[k].w, dot0);
            dot1 = fmaf(b.x, sv[k].x, dot1); dot1 = fmaf(b.y, sv[k].y, dot1);
            dot1 = fmaf(b.z, sv[k].z, dot1); dot1 = fmaf(b.w, sv[k].w, dot1);
        }
        #pragma unroll
        for (int o = 16; o; o >>= 1) {
            dot0 += __shfl_down_sync(0xffffffffu, dot0, o);
            dot1 += __shfl_down_sync(0xffffffffu, dot1, o);
        }
        if (lane == 0) {
            unsigned int u0 = __float_as_uint(dot0 * rinv0);
            unsigned int u1 = __float_as_uint(dot1 * rinv1);
            u0 = (u0 & 0x80000000u) ? ~u0 : (u0 | 0x80000000u);
            u1 = (u1 & 0x80000000u) ? ~u1 : (u1 | 0x80000000u);
            int row = blockIdx.x * 64 + lrow0;
            *(uint2*)&g_key[row] = make_uint2(u0, u1);
            atomicAdd(&g_hist[u0 >> 20], 1);
            atomicAdd(&g_hist[u1 >> 20], 1);
        }
    }

    // ===== SYNC 2: keys + hist visible. Blocks >= NTOP just arrive. ===========
    __syncthreads();
    if (t == 0) { __threadfence(); atomicAdd(&g_sync[1], 1u); }

    if (blockIdx.x < NTOP) {
        if (t == 0) {
            while (vload(&g_sync[1]) < NBLK) __nanosleep(32);
            __threadfence();
        }
        __syncthreads();

        // ===== P4: hist scan -> boundary bin B ================================
        unsigned int* ckey = (unsigned int*)sacc;          // [CAP]
        int*          cidx = (int*)sacc + CAP;             // [CAP]

        uint4 ka = ((const uint4*)g_key)[t];               // keys 4t..4t+3
        uint4 kb = ((const uint4*)g_key)[t + 1024];        // keys 4096+4t..
        uint4 hv = ((const uint4*)g_hist)[t];              // bins 4t..4t+3
        if (t == 0) sh_ncand = 0;

        int lsum = hv.x + hv.y + hv.z + hv.w;
        int v = lsum;
        #pragma unroll
        for (int o = 1; o < 32; o <<= 1) {
            int u = __shfl_up_sync(0xffffffffu, v, o);
            if (lane >= o) v += u;
        }
        if (lane == 31) swarp[wid] = v;
        __syncthreads();
        if (t < 32) {
            int w = swarp[t];
            int vv = w;
            #pragma unroll
            for (int o = 1; o < 32; o <<= 1) {
                int u = __shfl_up_sync(0xffffffffu, vv, o);
                if (lane >= o) vv += u;
            }
            swarp[t] = vv - w;                  // exclusive warp offset
        }
        __syncthreads();
        {
            int c = swarp[wid] + (v - lsum);
            int hh[4] = {(int)hv.x, (int)hv.y, (int)hv.z, (int)hv.w};
            #pragma unroll
            for (int i = 0; i < 4; ++i) {
                int c2 = c + hh[i];
                if (c < NTOP && c2 >= NTOP) sh_B = 4 * t + i;
                c = c2;
            }
        }
        __syncthreads();
        unsigned int B = (unsigned int)sh_B;

        // ===== collect candidates: warp-aggregated append =====================
        unsigned int keys[8] = {ka.x, ka.y, ka.z, ka.w, kb.x, kb.y, kb.z, kb.w};
        #pragma unroll
        for (int j = 0; j < 8; ++j) {
            bool hit = (keys[j] >> 20) <= B;
            unsigned int m = __ballot_sync(0xffffffffu, hit);
            if (m) {
                int cnt = __popc(m);
                int leader = __ffs(m) - 1;
                int base = 0;
                if (lane == leader) base = atomicAdd(&sh_ncand, cnt);
                base = __shfl_sync(0xffffffffu, base, leader);
                if (hit) {
                    int off = __popc(m & ((1u << lane) - 1u));
                    int p = base + off;
                    if (p < CAP) {
                        ckey[p] = keys[j];
                        cidx[p] = (j < 4) ? (4 * t + j) : (4096 + 4 * t + (j - 4));
                    }
                }
            }
        }
        __syncthreads();
        int nc = sh_ncand < CAP ? sh_ncand : CAP;

        if (t < nc) {
            unsigned int mk = ckey[t];
            int mi = cidx[t];
            int rank = 0;
            for (int j = 0; j < nc; ++j)
                rank += (ckey[j] < mk || (ckey[j] == mk && cidx[j] < mi)) ? 1 : 0;
            if (rank == blockIdx.x) s_row = mi;
        }
        __syncthreads();

        // ===== P5: write this block's row + index =============================
        int row = s_row;
        if (t < ND4) {
            int e = blockIdx.x * ND4 + t;
            if (4 * e + 4 <= out_size)
                out4[e] = x4[(size_t)row * ND4 + t];
        }
        if (t == 0 && NTOP * NDIM + blockIdx.x < out_size)
            out[NTOP * NDIM + blockIdx.x] = (float)row;
    }

    // ===== epilogue: last finisher resets g_s, g_hist, sync for replay ========
    __shared__ int s_reset;
    if (t == 0) {
        __threadfence();
        s_reset = (atomicAdd(&g_sync[2], 1u) == NBLK - 1) ? 1 : 0;
    }
    __syncthreads();
    if (s_reset) {
        if (t < ND4) g_s4[t] = make_float4(0.f, 0.f, 0.f, 0.f);
        #pragma unroll
        for (int j = 0; j < NBIN / NTHR; ++j) g_hist[t + NTHR * j] = 0;
        __syncthreads();
        if (t == 0) {
            *(volatile unsigned int*)&g_sync[0] = 0;
            *(volatile unsigned int*)&g_sync[1] = 0;
            __threadfence();
            *(volatile unsigned int*)&g_sync[2] = 0;
        }
    }
}

extern "C" void kernel_launch(void* const* d_in, const int* in_sizes, int n_in,
                              void* d_out, int out_size) {
    const float4* x4 = (const float4*)d_in[0];
    cudaFuncSetAttribute(kFused, cudaFuncAttributeMaxDynamicSharedMemorySize,
                         SMEM_TOTAL);
    kFused<<<NBLK, NTHR, SMEM_TOTAL>>>(x4, (float*)d_out, (float4*)d_out, out_size);
}

// round 15
// speedup vs baseline: 1.2092x; 1.1954x over previous
#include <cuda_runtime.h>

#define NROWS 8192
#define NDIM  512
#define ND4   128      // NDIM/4
#define NTOP  100
#define NBLK  128
#define NTHR  1024
#define NBIN  4096
#define CAP   1536

__device__ float4 g_s4v[ND4];          // column sum (zeroed by K3 each run)
__device__ float  g_rinv[NROWS];
__device__ unsigned int g_key[NROWS];

// ============================================================================
// K1: per-row 1/||x|| + column-sum of unit rows -> 512 REDs into g_s4v
// 128 blocks x 1024 thr, warp owns 2 rows.
// ============================================================================
__global__ void __launch_bounds__(NTHR, 1) k1(const float4* __restrict__ x4) {
    __shared__ float4 sacc[16 * ND4];        // 32 KB: 16 combined buffers
    __shared__ float  psum[2 * NDIM];        // 4 KB
    float* saccf = (float*)sacc;

    const int t    = threadIdx.x;
    const int wid  = t >> 5;
    const int lane = t & 31;
    const int row0 = blockIdx.x * 64 + wid * 2;

    const float4* r0 = x4 + (size_t)row0 * ND4;
    const float4* r1 = r0 + ND4;
    float4 v0[4], v1[4];
    #pragma unroll
    for (int k = 0; k < 4; ++k) v0[k] = r0[lane + 32 * k];
    #pragma unroll
    for (int k = 0; k < 4; ++k) v1[k] = r1[lane + 32 * k];

    float sq0 = 0.f, sq1 = 0.f;
    #pragma unroll
    for (int k = 0; k < 4; ++k) {
        sq0 += v0[k].x*v0[k].x + v0[k].y*v0[k].y + v0[k].z*v0[k].z + v0[k].w*v0[k].w;
        sq1 += v1[k].x*v1[k].x + v1[k].y*v1[k].y + v1[k].z*v1[k].z + v1[k].w*v1[k].w;
    }
    #pragma unroll
    for (int o = 16; o; o >>= 1) {
        sq0 += __shfl_xor_sync(0xffffffffu, sq0, o);
        sq1 += __shfl_xor_sync(0xffffffffu, sq1, o);
    }
    float rinv0 = rsqrtf(sq0);   // rel err ~2e-7 << rank-100 boundary gap ~1e-3
    float rinv1 = rsqrtf(sq1);
    if (lane == 0) *(float2*)&g_rinv[row0] = make_float2(rinv0, rinv1);

    float4 acc[4];
    #pragma unroll
    for (int k = 0; k < 4; ++k) {
        acc[k].x = fmaf(v0[k].x, rinv0, v1[k].x * rinv1);
        acc[k].y = fmaf(v0[k].y, rinv0, v1[k].y * rinv1);
        acc[k].z = fmaf(v0[k].z, rinv0, v1[k].z * rinv1);
        acc[k].w = fmaf(v0[k].w, rinv0, v1[k].w * rinv1);
    }
    // 32 warps -> 16 buffers
    if (wid >= 16) {
        #pragma unroll
        for (int k = 0; k < 4; ++k) sacc[(wid - 16) * ND4 + lane + 32 * k] = acc[k];
    }
    __syncthreads();
    if (wid < 16) {
        #pragma unroll
        for (int k = 0; k < 4; ++k) {
            float4 o = sacc[wid * ND4 + lane + 32 * k];
            acc[k].x += o.x; acc[k].y += o.y; acc[k].z += o.z; acc[k].w += o.w;
            sacc[wid * ND4 + lane + 32 * k] = acc[k];
        }
    }
    __syncthreads();
    // 1024 threads sum 8 buffers each (float-wise, conflict-free)
    {
        int d = t & (NDIM - 1);
        int g = t >> 9;                   // 0 or 1
        float s = 0.f;
        #pragma unroll
        for (int b = 0; b < 8; ++b) s += saccf[(g * 8 + b) * NDIM + d];
        psum[g * NDIM + d] = s;
    }
    __syncthreads();
    if (t < NDIM) atomicAdd((float*)g_s4v + t, psum[t] + psum[NDIM + t]);
}

// ============================================================================
// K2: scores from L2-resident x; order-preserving u32 keys.
// ============================================================================
__global__ void __launch_bounds__(NTHR, 1) k2(const float4* __restrict__ x4) {
    const int t    = threadIdx.x;
    const int wid  = t >> 5;
    const int lane = t & 31;
    const int row0 = blockIdx.x * 64 + wid * 2;

    float4 sv[4];
    #pragma unroll
    for (int k = 0; k < 4; ++k) sv[k] = g_s4v[lane + 32 * k];

    const float4* r0 = x4 + (size_t)row0 * ND4;
    const float4* r1 = r0 + ND4;
    float dot0 = 0.f, dot1 = 0.f;
    #pragma unroll
    for (int k = 0; k < 4; ++k) {
        float4 a = r0[lane + 32 * k];
        float4 b = r1[lane + 32 * k];
        dot0 = fmaf(a.x, sv[k].x, dot0); dot0 = fmaf(a.y, sv[k].y, dot0);
        dot0 = fmaf(a.z, sv[k].z, dot0); dot0 = fmaf(a.w, sv[k].w, dot0);
        dot1 = fmaf(b.x, sv[k].x, dot1); dot1 = fmaf(b.y, sv[k].y, dot1);
        dot1 = fmaf(b.z, sv[k].z, dot1); dot1 = fmaf(b.w, sv[k].w, dot1);
    }
    #pragma unroll
    for (int o = 16; o; o >>= 1) {
        dot0 += __shfl_down_sync(0xffffffffu, dot0, o);
        dot1 += __shfl_down_sync(0xffffffffu, dot1, o);
    }
    if (lane == 0) {
        float2 ri = *(const float2*)&g_rinv[row0];
        unsigned int u0 = __float_as_uint(dot0 * ri.x);
        unsigned int u1 = __float_as_uint(dot1 * ri.y);
        u0 = (u0 & 0x80000000u) ? ~u0 : (u0 | 0x80000000u);
        u1 = (u1 & 0x80000000u) ? ~u1 : (u1 | 0x80000000u);
        *(uint2*)&g_key[row0] = make_uint2(u0, u1);
    }
}

// ============================================================================
// K3: 100 blocks. Each: keys->regs, own smem hist, boundary bin, collect,
// exact stable rank; block b writes the rank-b row + index. Block 0 re-zeros
// g_s4v for the next graph replay (K2 already consumed it).
// ============================================================================
__global__ void __launch_bounds__(NTHR, 1) k3(const float4* __restrict__ x4,
                                              float* __restrict__ out,
                                              float4* __restrict__ out4,
                                              int out_size) {
    __shared__ int4 hist4[NBIN / 4];                 // 16 KB
    __shared__ unsigned int ckey[CAP];               // 6 KB
    __shared__ int cidx[CAP];                        // 6 KB
    __shared__ int swarp[32];
    __shared__ int sh_B, sh_ncand, s_row;
    int* hist = (int*)hist4;

    const int t    = threadIdx.x;
    const int wid  = t >> 5;
    const int lane = t & 31;

    uint4 ka = ((const uint4*)g_key)[t];
    uint4 kb = ((const uint4*)g_key)[t + 1024];
    unsigned int keys[8] = {ka.x, ka.y, ka.z, ka.w, kb.x, kb.y, kb.z, kb.w};

    #pragma unroll
    for (int j = 0; j < NBIN / NTHR; ++j) hist[t + NTHR * j] = 0;
    if (t == 0) sh_ncand = 0;
    __syncthreads();

    #pragma unroll
    for (int j = 0; j < 8; ++j) atomicAdd(&hist[keys[j] >> 20], 1);
    __syncthreads();

    // scan 4096 bins (4/thread) for boundary bin B
    int4 hv = hist4[t];
    int hh[4] = {hv.x, hv.y, hv.z, hv.w};
    int lsum = hh[0] + hh[1] + hh[2] + hh[3];
    int v = lsum;
    #pragma unroll
    for (int o = 1; o < 32; o <<= 1) {
        int u = __shfl_up_sync(0xffffffffu, v, o);
        if (lane >= o) v += u;
    }
    if (lane == 31) swarp[wid] = v;
    __syncthreads();
    if (t < 32) {
        int w = swarp[t];
        int vv = w;
        #pragma unroll
        for (int o = 1; o < 32; o <<= 1) {
            int u = __shfl_up_sync(0xffffffffu, vv, o);
            if (lane >= o) vv += u;
        }
        swarp[t] = vv - w;
    }
    __syncthreads();
    {
        int c = swarp[wid] + (v - lsum);
        #pragma unroll
        for (int i = 0; i < 4; ++i) {
            int c2 = c + hh[i];
            if (c < NTOP && c2 >= NTOP) sh_B = 4 * t + i;
            c = c2;
        }
    }
    __syncthreads();
    unsigned int B = (unsigned int)sh_B;

    // collect candidates (warp-aggregated append)
    #pragma unroll
    for (int j = 0; j < 8; ++j) {
        bool hit = (keys[j] >> 20) <= B;
        unsigned int m = __ballot_sync(0xffffffffu, hit);
        if (m) {
            int cnt = __popc(m);
            int leader = __ffs(m) - 1;
            int base = 0;
            if (lane == leader) base = atomicAdd(&sh_ncand, cnt);
            base = __shfl_sync(0xffffffffu, base, leader);
            if (hit) {
                int p = base + __popc(m & ((1u << lane) - 1u));
                if (p < CAP) {
                    ckey[p] = keys[j];
                    cidx[p] = (j < 4) ? (4 * t + j) : (4096 + 4 * t + (j - 4));
                }
            }
        }
    }
    __syncthreads();
    int nc = sh_ncand < CAP ? sh_ncand : CAP;

    if (t < nc) {
        unsigned int mk = ckey[t];
        int mi = cidx[t];
        int rank = 0;
        for (int j = 0; j < nc; ++j)
            rank += (ckey[j] < mk || (ckey[j] == mk && cidx[j] < mi)) ? 1 : 0;
        if (rank == blockIdx.x) s_row = mi;
    }
    __syncthreads();

    int row = s_row;
    if (t < ND4) {
        int e = blockIdx.x * ND4 + t;
        if (4 * e + 4 <= out_size)
            out4[e] = x4[(size_t)row * ND4 + t];
    }
    if (t == 0 && NTOP * NDIM + blockIdx.x < out_size)
        out[NTOP * NDIM + blockIdx.x] = (float)row;

    // block 0 restores the replay invariant (g_s4v == 0); K2 is already done
    if (blockIdx.x == 0 && t < ND4)
        g_s4v[t] = make_float4(0.f, 0.f, 0.f, 0.f);
}

extern "C" void kernel_launch(void* const* d_in, const int* in_sizes, int n_in,
                              void* d_out, int out_size) {
    const float4* x4 = (const float4*)d_in[0];
    k1<<<NBLK, NTHR>>>(x4);
    k2<<<NBLK, NTHR>>>(x4);
    k3<<<NTOP, NTHR>>>(x4, (float*)d_out, (float4*)d_out, out_size);
}